// round 2
// baseline (speedup 1.0000x reference)
#include <cuda_runtime.h>
#include <math.h>

#define SQ    4096
#define HIDN  2048
#define NHEADS 16
#define NKVH   4
#define HDIM   128
#define KVW   (NKVH * HDIM)   // 512

// ---------------- scratch (static device globals; no allocation) ----------------
__device__ float g_Q[SQ * HIDN];          // 32 MB
__device__ float g_K[SQ * KVW];           // 8 MB
__device__ float g_V[SQ * KVW];           // 8 MB
__device__ float g_AO[SQ * HIDN];         // 32 MB

// ============================================================================
// SGEMM: C[M,N] = A[M,K] @ B[K,N], row-major, 128x128 tile, 8x8 microtile
// ============================================================================
__global__ __launch_bounds__(256) void sgemm128(
    const float* __restrict__ A, const float* __restrict__ B,
    float* __restrict__ C, int M, int N, int K)
{
    __shared__ float As[8][128];
    __shared__ float Bs[8][128];

    const int tid = threadIdx.x;
    const int bm = blockIdx.y * 128;
    const int bn = blockIdx.x * 128;
    const int ty = tid >> 4;           // 0..15
    const int tx = tid & 15;           // 0..15

    const int arow = tid >> 1;         // 0..127
    const int ac4  = (tid & 1) << 2;   // 0 or 4
    const int brw  = tid >> 5;         // 0..7
    const int bc4  = (tid & 31) << 2;  // 0..124

    float acc[8][8];
    #pragma unroll
    for (int i = 0; i < 8; i++)
        #pragma unroll
        for (int j = 0; j < 8; j++) acc[i][j] = 0.0f;

    for (int k0 = 0; k0 < K; k0 += 8) {
        float4 a = *(const float4*)(A + (size_t)(bm + arow) * K + k0 + ac4);
        As[ac4 + 0][arow] = a.x;
        As[ac4 + 1][arow] = a.y;
        As[ac4 + 2][arow] = a.z;
        As[ac4 + 3][arow] = a.w;
        float4 b = *(const float4*)(B + (size_t)(k0 + brw) * N + bn + bc4);
        *(float4*)(&Bs[brw][bc4]) = b;
        __syncthreads();

        #pragma unroll
        for (int kk = 0; kk < 8; kk++) {
            float ra[8], rb[8];
            *(float4*)(&ra[0]) = *(const float4*)(&As[kk][ty * 8]);
            *(float4*)(&ra[4]) = *(const float4*)(&As[kk][ty * 8 + 4]);
            *(float4*)(&rb[0]) = *(const float4*)(&Bs[kk][tx * 8]);
            *(float4*)(&rb[4]) = *(const float4*)(&Bs[kk][tx * 8 + 4]);
            #pragma unroll
            for (int i = 0; i < 8; i++)
                #pragma unroll
                for (int j = 0; j < 8; j++)
                    acc[i][j] = fmaf(ra[i], rb[j], acc[i][j]);
        }
        __syncthreads();
    }

    #pragma unroll
    for (int i = 0; i < 8; i++) {
        float4 v0 = make_float4(acc[i][0], acc[i][1], acc[i][2], acc[i][3]);
        float4 v1 = make_float4(acc[i][4], acc[i][5], acc[i][6], acc[i][7]);
        float* cp = C + (size_t)(bm + ty * 8 + i) * N + bn + tx * 8;
        *(float4*)(cp)     = v0;
        *(float4*)(cp + 4) = v1;
    }
}

// ============================================================================
// RoPE: in-place on Q [S, 2048] and K [S, 512]
// ============================================================================
__global__ void rope_kernel(float* __restrict__ Q, float* __restrict__ K,
                            const int* __restrict__ pos_ids)
{
    __shared__ float s_inv[64];
    const int s = blockIdx.x;
    if (threadIdx.x < 64) {
        // inv_freq[d] = theta^(-d/64) = exp2(-d/64 * log2(10000)), in double
        // to match the reference's fp32 pow to <=1 ulp.
        s_inv[threadIdx.x] =
            (float)exp2(-(double)threadIdx.x * (13.287712379549449 / 64.0));
    }
    __syncthreads();

    const float p = (float)pos_ids[s];
    for (int idx = threadIdx.x; idx < (NHEADS + NKVH) * 64; idx += blockDim.x) {
        float* base;
        int d;
        if (idx < NHEADS * 64) {
            int h = idx >> 6; d = idx & 63;
            base = Q + (size_t)s * HIDN + h * HDIM;
        } else {
            int t = idx - NHEADS * 64;
            int h = t >> 6; d = t & 63;
            base = K + (size_t)s * KVW + h * HDIM;
        }
        float ang = p * s_inv[d];
        float sn, cs;
        sincosf(ang, &sn, &cs);
        float x1 = base[d], x2 = base[d + 64];
        base[d]      = x1 * cs - x2 * sn;
        base[d + 64] = x2 * cs + x1 * sn;
    }
}

// ============================================================================
// Flash attention (fp32, causal, GQA 4:1)
// grid: (S/64, NH).  256 threads.  BQ=BK=64.
// smem: Qt[128][64] (d-major, xor-swizzled), Kt same, Vs[64][128], Ps[64][64]
// ============================================================================
#define ATTN_SMEM ((8192 * 3 + 4096) * 4)   // 114688 B

__global__ __launch_bounds__(256) void attn_kernel(
    const float* __restrict__ Q, const float* __restrict__ K,
    const float* __restrict__ V, float* __restrict__ O)
{
    extern __shared__ float sm[];
    float* Qt = sm;                 // [128][64] phys: d*64 + (row ^ swz(d))
    float* Kt = Qt + 128 * 64;      // [128][64] same layout
    float* Vs = Kt + 128 * 64;      // [64][128] natural
    float* Ps = Vs + 64 * 128;      // [64][64]  natural

    const int qb  = blockIdx.x;     // 0..63
    const int h   = blockIdx.y;     // 0..15
    const int kvh = h >> 2;         // GQA: 4 q-heads per kv-head
    const int qbase = qb * 64;
    const int tid = threadIdx.x;
    const int ty  = tid >> 4;       // 0..15 (query rows ty*4..+3)
    const int tx  = tid & 15;       // 0..15 (key cols tx*4..+3 / out cols tx*8..+7)

    // ---- load Q tile, transposed + swizzled ----
    for (int idx = tid; idx < 2048; idx += 256) {
        int row = idx >> 5;                 // 0..63
        int c4  = (idx & 31) << 2;          // d base
        float4 qv = *(const float4*)(Q + (size_t)(qbase + row) * HIDN + h * HDIM + c4);
        int sw = ((c4 >> 2) & 15) << 2;
        int rs = row ^ sw;
        Qt[(c4 + 0) * 64 + rs] = qv.x;
        Qt[(c4 + 1) * 64 + rs] = qv.y;
        Qt[(c4 + 2) * 64 + rs] = qv.z;
        Qt[(c4 + 3) * 64 + rs] = qv.w;
    }

    float m_run[4], l_run[4], o_acc[4][8];
    #pragma unroll
    for (int i = 0; i < 4; i++) {
        m_run[i] = -3.0e38f;
        l_run[i] = 0.0f;
        #pragma unroll
        for (int j = 0; j < 8; j++) o_acc[i][j] = 0.0f;
    }

    const float scale = 0.08838834764831845f;   // 1/sqrt(128)

    for (int kb = 0; kb <= qb; kb++) {
        const int kbase = kb * 64;
        const bool diag = (kb == qb);

        __syncthreads();   // protect Kt/Vs/Ps from previous iteration

        // ---- load K (transposed+swizzled) and V (natural) tiles ----
        for (int idx = tid; idx < 2048; idx += 256) {
            int row = idx >> 5;
            int c4  = (idx & 31) << 2;
            const float* kp = K + (size_t)(kbase + row) * KVW + kvh * HDIM + c4;
            const float* vp = V + (size_t)(kbase + row) * KVW + kvh * HDIM + c4;
            float4 kv = *(const float4*)kp;
            int sw = ((c4 >> 2) & 15) << 2;
            int rs = row ^ sw;
            Kt[(c4 + 0) * 64 + rs] = kv.x;
            Kt[(c4 + 1) * 64 + rs] = kv.y;
            Kt[(c4 + 2) * 64 + rs] = kv.z;
            Kt[(c4 + 3) * 64 + rs] = kv.w;
            float4 vv = *(const float4*)vp;
            *(float4*)(&Vs[row * 128 + c4]) = vv;
        }
        __syncthreads();

        // ---- S = Q @ K^T  (64x64, k-dim = 128) ----
        float s_acc[4][4];
        #pragma unroll
        for (int i = 0; i < 4; i++)
            #pragma unroll
            for (int j = 0; j < 4; j++) s_acc[i][j] = 0.0f;

        #pragma unroll 4
        for (int d4 = 0; d4 < 32; d4++) {
            const int sw = (d4 & 15) << 2;
            const float* qp = &Qt[(d4 * 4) * 64 + ((ty << 2) ^ sw)];
            const float* kp = &Kt[(d4 * 4) * 64 + ((tx << 2) ^ sw)];
            #pragma unroll
            for (int u = 0; u < 4; u++) {
                float4 ra = *(const float4*)(qp + u * 64);
                float4 rb = *(const float4*)(kp + u * 64);
                float av[4] = {ra.x, ra.y, ra.z, ra.w};
                float bv[4] = {rb.x, rb.y, rb.z, rb.w};
                #pragma unroll
                for (int i = 0; i < 4; i++)
                    #pragma unroll
                    for (int j = 0; j < 4; j++)
                        s_acc[i][j] = fmaf(av[i], bv[j], s_acc[i][j]);
            }
        }

        // ---- scale + causal mask + online softmax ----
        #pragma unroll
        for (int i = 0; i < 4; i++) {
            float mx = -3.0e38f;
            #pragma unroll
            for (int j = 0; j < 4; j++) {
                float v = s_acc[i][j] * scale;
                if (diag && (kbase + (tx << 2) + j > qbase + (ty << 2) + i))
                    v = -3.0e38f;
                s_acc[i][j] = v;
                mx = fmaxf(mx, v);
            }
            #pragma unroll
            for (int o = 8; o >= 1; o >>= 1)
                mx = fmaxf(mx, __shfl_xor_sync(0xffffffffu, mx, o));

            float mnew  = fmaxf(m_run[i], mx);
            float alpha = __expf(m_run[i] - mnew);
            float rs = 0.0f;
            #pragma unroll
            for (int j = 0; j < 4; j++) {
                float pj = __expf(s_acc[i][j] - mnew);
                s_acc[i][j] = pj;
                rs += pj;
            }
            #pragma unroll
            for (int o = 8; o >= 1; o >>= 1)
                rs += __shfl_xor_sync(0xffffffffu, rs, o);

            l_run[i] = l_run[i] * alpha + rs;
            m_run[i] = mnew;
            #pragma unroll
            for (int jo = 0; jo < 8; jo++) o_acc[i][jo] *= alpha;
        }

        // ---- stage P to smem ----
        #pragma unroll
        for (int i = 0; i < 4; i++) {
            *(float4*)(&Ps[(ty * 4 + i) * 64 + tx * 4]) =
                make_float4(s_acc[i][0], s_acc[i][1], s_acc[i][2], s_acc[i][3]);
        }
        __syncthreads();

        // ---- O += P @ V  (64x128, k-dim = 64 keys) ----
        #pragma unroll 4
        for (int k = 0; k < 64; k++) {
            float pa[4];
            #pragma unroll
            for (int i = 0; i < 4; i++) pa[i] = Ps[(ty * 4 + i) * 64 + k];
            float4 vb0 = *(const float4*)(&Vs[k * 128 + tx * 8]);
            float4 vb1 = *(const float4*)(&Vs[k * 128 + tx * 8 + 4]);
            float bv[8] = {vb0.x, vb0.y, vb0.z, vb0.w, vb1.x, vb1.y, vb1.z, vb1.w};
            #pragma unroll
            for (int i = 0; i < 4; i++)
                #pragma unroll
                for (int jo = 0; jo < 8; jo++)
                    o_acc[i][jo] = fmaf(pa[i], bv[jo], o_acc[i][jo]);
        }
    }

    // ---- normalize and write AO[s, h*128 + d] ----
    #pragma unroll
    for (int i = 0; i < 4; i++) {
        float invl = 1.0f / l_run[i];
        float* op = O + (size_t)(qbase + ty * 4 + i) * HIDN + h * HDIM + tx * 8;
        float4 v0 = make_float4(o_acc[i][0] * invl, o_acc[i][1] * invl,
                                o_acc[i][2] * invl, o_acc[i][3] * invl);
        float4 v1 = make_float4(o_acc[i][4] * invl, o_acc[i][5] * invl,
                                o_acc[i][6] * invl, o_acc[i][7] * invl);
        *(float4*)(op)     = v0;
        *(float4*)(op + 4) = v1;
    }
}

// ============================================================================
// launch
// ============================================================================
extern "C" void kernel_launch(void* const* d_in, const int* in_sizes, int n_in,
                              void* d_out, int out_size)
{
    const float* X   = (const float*)d_in[0];
    const int*   pid = (const int*)  d_in[1];
    const float* Wq  = (const float*)d_in[2];
    const float* Wk  = (const float*)d_in[3];
    const float* Wv  = (const float*)d_in[4];
    const float* Wo  = (const float*)d_in[5];
    float* out = (float*)d_out;

    float *Qb, *Kb, *Vb, *AOb;
    cudaGetSymbolAddress((void**)&Qb,  g_Q);
    cudaGetSymbolAddress((void**)&Kb,  g_K);
    cudaGetSymbolAddress((void**)&Vb,  g_V);
    cudaGetSymbolAddress((void**)&AOb, g_AO);

    dim3 gq(HIDN / 128, SQ / 128);     // 16 x 32
    dim3 gkv(KVW / 128, SQ / 128);     // 4 x 32

    sgemm128<<<gq, 256>>>(X, Wq, Qb, SQ, HIDN, HIDN);
    sgemm128<<<gkv, 256>>>(X, Wk, Kb, SQ, KVW, HIDN);
    sgemm128<<<gkv, 256>>>(X, Wv, Vb, SQ, KVW, HIDN);

    rope_kernel<<<SQ, 256>>>(Qb, Kb, pid);

    cudaFuncSetAttribute(attn_kernel,
                         cudaFuncAttributeMaxDynamicSharedMemorySize, ATTN_SMEM);
    dim3 ga(SQ / 64, NHEADS);          // 64 x 16
    attn_kernel<<<ga, 256, ATTN_SMEM>>>(Qb, Kb, Vb, AOb);

    sgemm128<<<gq, 256>>>(AOb, Wo, out, SQ, HIDN, HIDN);
}

// round 5
// speedup vs baseline: 4.1321x; 4.1321x over previous
#include <cuda_runtime.h>
#include <math.h>

#define SQ    4096
#define HIDN  2048
#define NHEADS 16
#define NKVH   4
#define HDIM   128
#define KVW   (NKVH * HDIM)   // 512

// ---------------- scratch (static device globals; no allocation) ----------------
__device__ float g_Q[SQ * HIDN];          // 32 MB
__device__ float g_K[SQ * KVW];           // 8 MB
__device__ float g_V[SQ * KVW];           // 8 MB
__device__ float g_AO[SQ * HIDN];         // 32 MB

// ---------------- PTX helpers ----------------
__device__ __forceinline__ unsigned smem_u32(const void* p) {
    return (unsigned)__cvta_generic_to_shared(p);
}
__device__ __forceinline__ void cp_async16(unsigned dst, const void* src) {
    asm volatile("cp.async.cg.shared.global [%0], [%1], 16;\n" :: "r"(dst), "l"(src));
}
__device__ __forceinline__ void cp_commit() {
    asm volatile("cp.async.commit_group;\n");
}
template<int N> __device__ __forceinline__ void cp_wait() {
    asm volatile("cp.async.wait_group %0;\n" :: "n"(N));
}
__device__ __forceinline__ unsigned f2tf(float f) {
    unsigned u;
    asm("cvt.rna.tf32.f32 %0, %1;" : "=r"(u) : "f"(f));
    return u;
}
__device__ __forceinline__ void mma_tf32(float& c0, float& c1, float& c2, float& c3,
                                         unsigned a0, unsigned a1, unsigned a2, unsigned a3,
                                         unsigned b0, unsigned b1) {
    asm volatile("mma.sync.aligned.m16n8k8.row.col.f32.tf32.tf32.f32 "
                 "{%0,%1,%2,%3},{%4,%5,%6,%7},{%8,%9},{%0,%1,%2,%3};"
                 : "+f"(c0), "+f"(c1), "+f"(c2), "+f"(c3)
                 : "r"(a0), "r"(a1), "r"(a2), "r"(a3), "r"(b0), "r"(b1));
}

// ============================================================================
// TF32 tensor-core GEMM: C[M,N] = A[M,K] @ B[K,N], row-major.
// 128x128 CTA tile, BK=16, 3-stage cp.async pipeline, 8 warps (2m x 4n),
// warp tile 64x32 via m16n8k8 mma. A smem stride 20, B stride 136.
// ============================================================================
#define GBM 128
#define GBN 128
#define GBK 16
#define GSTG 3
#define ASTR 20
#define BSTR 136
#define GEMM_SMEM (GSTG * (GBM * ASTR + GBK * BSTR) * 4)   // 56832 B

__global__ __launch_bounds__(256, 2) void sgemm_tf32(
    const float* __restrict__ A, const float* __restrict__ B,
    float* __restrict__ C, int M, int N, int K)
{
    extern __shared__ float sh[];
    float* As = sh;                            // GSTG stages of [128][20]
    float* Bs = sh + GSTG * GBM * ASTR;        // GSTG stages of [16][136]

    const int tid  = threadIdx.x;
    const int lane = tid & 31, warp = tid >> 5;
    const int g = lane >> 2, t = lane & 3;
    const int wm = warp >> 2, wn = warp & 3;
    const int bm = blockIdx.y * GBM, bn = blockIdx.x * GBN;

    float acc[4][4][4];
    #pragma unroll
    for (int mt = 0; mt < 4; mt++)
        #pragma unroll
        for (int nt = 0; nt < 4; nt++)
            #pragma unroll
            for (int i = 0; i < 4; i++) acc[mt][nt][i] = 0.0f;

    auto issue = [&](int it) {
        int stage = it % GSTG;
        int k0 = it * GBK;
        float* as = As + stage * GBM * ASTR;
        float* bs = Bs + stage * GBK * BSTR;
        #pragma unroll
        for (int j = 0; j < 2; j++) {
            int ch = tid + 256 * j;        // 512 A chunks (128 rows x 4)
            int r = ch >> 2, c = ch & 3;
            cp_async16(smem_u32(as + r * ASTR + c * 4),
                       A + (size_t)(bm + r) * K + k0 + c * 4);
        }
        #pragma unroll
        for (int j = 0; j < 2; j++) {
            int ch = tid + 256 * j;        // 512 B chunks (16 rows x 32)
            int r = ch >> 5, c = ch & 31;
            cp_async16(smem_u32(bs + r * BSTR + c * 4),
                       B + (size_t)(k0 + r) * N + bn + c * 4);
        }
    };

    const int NK = K / GBK;
    issue(0); cp_commit();
    issue(1); cp_commit();

    for (int it = 0; it < NK; it++) {
        cp_wait<1>();
        __syncthreads();
        if (it + 2 < NK) issue(it + 2);
        cp_commit();

        int stage = it % GSTG;
        const float* as = As + stage * GBM * ASTR + (wm * 64) * ASTR;
        const float* bs = Bs + stage * GBK * BSTR + wn * 32;

        #pragma unroll
        for (int ks = 0; ks < 2; ks++) {
            unsigned af[4][4], bf[4][2];
            #pragma unroll
            for (int mt = 0; mt < 4; mt++) {
                const float* p = as + (mt * 16 + g) * ASTR + ks * 8 + t;
                af[mt][0] = f2tf(p[0]);
                af[mt][1] = f2tf(p[8 * ASTR]);
                af[mt][2] = f2tf(p[4]);
                af[mt][3] = f2tf(p[8 * ASTR + 4]);
            }
            #pragma unroll
            for (int nt = 0; nt < 4; nt++) {
                const float* p = bs + (ks * 8 + t) * BSTR + nt * 8 + g;
                bf[nt][0] = f2tf(p[0]);
                bf[nt][1] = f2tf(p[4 * BSTR]);
            }
            #pragma unroll
            for (int mt = 0; mt < 4; mt++)
                #pragma unroll
                for (int nt = 0; nt < 4; nt++)
                    mma_tf32(acc[mt][nt][0], acc[mt][nt][1], acc[mt][nt][2], acc[mt][nt][3],
                             af[mt][0], af[mt][1], af[mt][2], af[mt][3],
                             bf[nt][0], bf[nt][1]);
        }
    }

    #pragma unroll
    for (int mt = 0; mt < 4; mt++) {
        int row0 = bm + wm * 64 + mt * 16 + g;
        #pragma unroll
        for (int nt = 0; nt < 4; nt++) {
            int col = bn + wn * 32 + nt * 8 + 2 * t;
            float2 v0 = make_float2(acc[mt][nt][0], acc[mt][nt][1]);
            float2 v1 = make_float2(acc[mt][nt][2], acc[mt][nt][3]);
            *(float2*)(C + (size_t)row0 * N + col)       = v0;
            *(float2*)(C + (size_t)(row0 + 8) * N + col) = v1;
        }
    }
}

// ============================================================================
// RoPE in-place on Q [S,2048] and K [S,512]; rounds K and V to tf32.
// ============================================================================
__global__ void rope_kernel(float* __restrict__ Q, float* __restrict__ K,
                            float* __restrict__ V, const int* __restrict__ pos_ids)
{
    __shared__ float s_inv[64];
    const int s = blockIdx.x;
    if (threadIdx.x < 64) {
        s_inv[threadIdx.x] =
            (float)exp2(-(double)threadIdx.x * (13.287712379549449 / 64.0));
    }
    __syncthreads();

    const float p = (float)pos_ids[s];
    for (int idx = threadIdx.x; idx < (NHEADS + NKVH) * 64; idx += blockDim.x) {
        float* base;
        int d;
        bool isK;
        if (idx < NHEADS * 64) {
            int h = idx >> 6; d = idx & 63;
            base = Q + (size_t)s * HIDN + h * HDIM;
            isK = false;
        } else {
            int tt = idx - NHEADS * 64;
            int h = tt >> 6; d = tt & 63;
            base = K + (size_t)s * KVW + h * HDIM;
            isK = true;
        }
        float ang = p * s_inv[d];
        float sn, cs;
        sincosf(ang, &sn, &cs);
        float x1 = base[d], x2 = base[d + 64];
        float r1 = x1 * cs - x2 * sn;
        float r2 = x2 * cs + x1 * sn;
        if (isK) { r1 = __uint_as_float(f2tf(r1)); r2 = __uint_as_float(f2tf(r2)); }
        base[d]      = r1;
        base[d + 64] = r2;
    }
    for (int idx = threadIdx.x; idx < KVW; idx += blockDim.x) {
        float v = V[(size_t)s * KVW + idx];
        V[(size_t)s * KVW + idx] = __uint_as_float(f2tf(v));
    }
}

// ============================================================================
// Tensor-core flash attention (tf32 mma, fp32 accum, causal, GQA 4:1).
// BQ=128 (8 warps x m16), BK=64. Q fragments in registers (pre-scaled, tf32).
// K/V double-buffered cp.async. P via padded smem (warp-private rows).
// ============================================================================
#define KSTR 132
#define VSTR 136
#define PSTR 68
#define ATTN_SMEM ((2*64*KSTR + 2*64*VSTR + 128*PSTR) * 4)   // 172032 B

__global__ __launch_bounds__(256, 1) void attn_tc(
    const float* __restrict__ Q, const float* __restrict__ K,
    const float* __restrict__ V, float* __restrict__ O)
{
    extern __shared__ float sh[];
    float* Ks = sh;                       // 2 stages [64][132]
    float* Vs = sh + 2 * 64 * KSTR;       // 2 stages [64][136]
    float* Ps = Vs + 2 * 64 * VSTR;       // [128][68]

    const int tid = threadIdx.x, lane = tid & 31, warp = tid >> 5;
    const int g = lane >> 2, t = lane & 3;
    const int h = blockIdx.x;
    const int q = (int)(gridDim.y - 1 - blockIdx.y);   // heavy tiles first
    const int qbase = q * 128;
    const int kvh = h >> 2;
    const int niter = 2 * q + 2;
    const float scale = 0.08838834764831845f;          // 1/sqrt(128)

    // ---- Q fragments into registers (pre-scaled, tf32) ----
    unsigned qa[16][4];
    {
        const float* qp  = Q + (size_t)(qbase + warp * 16 + g) * HIDN + h * HDIM;
        const float* qp8 = qp + 8 * HIDN;
        #pragma unroll
        for (int ks = 0; ks < 16; ks++) {
            qa[ks][0] = f2tf(scale * qp [ks * 8 + t]);
            qa[ks][1] = f2tf(scale * qp8[ks * 8 + t]);
            qa[ks][2] = f2tf(scale * qp [ks * 8 + t + 4]);
            qa[ks][3] = f2tf(scale * qp8[ks * 8 + t + 4]);
        }
    }

    float oacc[16][4];
    #pragma unroll
    for (int nt = 0; nt < 16; nt++)
        #pragma unroll
        for (int i = 0; i < 4; i++) oacc[nt][i] = 0.0f;
    float m0 = -1e30f, m1 = -1e30f, l0 = 0.0f, l1 = 0.0f;

    // FIX (round 3): a 64x128 tile is 2048 float4 chunks, not 512.
    // j runs 0..7; r = ch>>5 covers all 64 rows, c = ch&31 covers all 128 cols.
    auto issueKV = [&](int kb) {
        int stage = kb & 1;
        float* kd = Ks + stage * 64 * KSTR;
        float* vd = Vs + stage * 64 * VSTR;
        const float* kg = K + (size_t)(kb * 64) * KVW + kvh * HDIM;
        const float* vg = V + (size_t)(kb * 64) * KVW + kvh * HDIM;
        #pragma unroll
        for (int j = 0; j < 8; j++) {
            int ch = tid + 256 * j;          // 2048 chunks
            int r = ch >> 5, c = ch & 31;
            cp_async16(smem_u32(kd + r * KSTR + c * 4), kg + (size_t)r * KVW + c * 4);
        }
        #pragma unroll
        for (int j = 0; j < 8; j++) {
            int ch = tid + 256 * j;
            int r = ch >> 5, c = ch & 31;
            cp_async16(smem_u32(vd + r * VSTR + c * 4), vg + (size_t)r * KVW + c * 4);
        }
    };
    issueKV(0); cp_commit();
    issueKV(1); cp_commit();                 // niter >= 2 always

    for (int kb = 0; kb < niter; kb++) {
        int stage = kb & 1;
        cp_wait<1>();
        __syncthreads();
        const float* kd = Ks + stage * 64 * KSTR;
        const float* vd = Vs + stage * 64 * VSTR;

        // ---- S = (Q*scale) @ K^T ----
        float sacc[8][4];
        #pragma unroll
        for (int nt = 0; nt < 8; nt++)
            #pragma unroll
            for (int i = 0; i < 4; i++) sacc[nt][i] = 0.0f;

        #pragma unroll
        for (int ks = 0; ks < 16; ks++) {
            #pragma unroll
            for (int nt = 0; nt < 8; nt++) {
                const float* bp = kd + (nt * 8 + g) * KSTR + ks * 8 + t;
                unsigned b0 = __float_as_uint(bp[0]);
                unsigned b1 = __float_as_uint(bp[4]);
                mma_tf32(sacc[nt][0], sacc[nt][1], sacc[nt][2], sacc[nt][3],
                         qa[ks][0], qa[ks][1], qa[ks][2], qa[ks][3], b0, b1);
            }
        }

        // ---- causal mask (only the last two k-tiles intersect the diagonal) ----
        const int row0 = qbase + warp * 16 + g;
        if (kb >= niter - 2) {
            #pragma unroll
            for (int nt = 0; nt < 8; nt++) {
                int c0 = kb * 64 + nt * 8 + 2 * t;
                if (c0     > row0)     sacc[nt][0] = -1e30f;
                if (c0 + 1 > row0)     sacc[nt][1] = -1e30f;
                if (c0     > row0 + 8) sacc[nt][2] = -1e30f;
                if (c0 + 1 > row0 + 8) sacc[nt][3] = -1e30f;
            }
        }

        // ---- online softmax (rows g and g+8; reduce over the 4-lane quad) ----
        float mx0 = -1e30f, mx1 = -1e30f;
        #pragma unroll
        for (int nt = 0; nt < 8; nt++) {
            mx0 = fmaxf(mx0, fmaxf(sacc[nt][0], sacc[nt][1]));
            mx1 = fmaxf(mx1, fmaxf(sacc[nt][2], sacc[nt][3]));
        }
        mx0 = fmaxf(mx0, __shfl_xor_sync(0xffffffffu, mx0, 1));
        mx0 = fmaxf(mx0, __shfl_xor_sync(0xffffffffu, mx0, 2));
        mx1 = fmaxf(mx1, __shfl_xor_sync(0xffffffffu, mx1, 1));
        mx1 = fmaxf(mx1, __shfl_xor_sync(0xffffffffu, mx1, 2));

        float nm0 = fmaxf(m0, mx0), nm1 = fmaxf(m1, mx1);
        float al0 = __expf(m0 - nm0), al1 = __expf(m1 - nm1);
        float s0 = 0.0f, s1 = 0.0f;
        #pragma unroll
        for (int nt = 0; nt < 8; nt++) {
            sacc[nt][0] = __expf(sacc[nt][0] - nm0); s0 += sacc[nt][0];
            sacc[nt][1] = __expf(sacc[nt][1] - nm0); s0 += sacc[nt][1];
            sacc[nt][2] = __expf(sacc[nt][2] - nm1); s1 += sacc[nt][2];
            sacc[nt][3] = __expf(sacc[nt][3] - nm1); s1 += sacc[nt][3];
        }
        s0 += __shfl_xor_sync(0xffffffffu, s0, 1);
        s0 += __shfl_xor_sync(0xffffffffu, s0, 2);
        s1 += __shfl_xor_sync(0xffffffffu, s1, 1);
        s1 += __shfl_xor_sync(0xffffffffu, s1, 2);

        l0 = l0 * al0 + s0;  l1 = l1 * al1 + s1;
        m0 = nm0;            m1 = nm1;
        #pragma unroll
        for (int nt = 0; nt < 16; nt++) {
            oacc[nt][0] *= al0; oacc[nt][1] *= al0;
            oacc[nt][2] *= al1; oacc[nt][3] *= al1;
        }

        // ---- stage P (tf32) to warp-private smem rows ----
        unsigned* pw0 = (unsigned*)(Ps + (warp * 16 + g) * PSTR);
        unsigned* pw1 = pw0 + 8 * PSTR;
        #pragma unroll
        for (int nt = 0; nt < 8; nt++) {
            pw0[nt * 8 + 2 * t]     = f2tf(sacc[nt][0]);
            pw0[nt * 8 + 2 * t + 1] = f2tf(sacc[nt][1]);
            pw1[nt * 8 + 2 * t]     = f2tf(sacc[nt][2]);
            pw1[nt * 8 + 2 * t + 1] = f2tf(sacc[nt][3]);
        }
        __syncwarp();

        // ---- O += P @ V ----
        const unsigned* pr = (const unsigned*)(Ps + (warp * 16 + g) * PSTR);
        #pragma unroll
        for (int ks = 0; ks < 8; ks++) {
            unsigned a0 = pr[ks * 8 + t];
            unsigned a1 = pr[8 * PSTR + ks * 8 + t];
            unsigned a2 = pr[ks * 8 + t + 4];
            unsigned a3 = pr[8 * PSTR + ks * 8 + t + 4];
            #pragma unroll
            for (int nt = 0; nt < 16; nt++) {
                const float* vp = vd + (ks * 8 + t) * VSTR + nt * 8 + g;
                unsigned b0 = __float_as_uint(vp[0]);
                unsigned b1 = __float_as_uint(vp[4 * VSTR]);
                mma_tf32(oacc[nt][0], oacc[nt][1], oacc[nt][2], oacc[nt][3],
                         a0, a1, a2, a3, b0, b1);
            }
        }

        __syncthreads();                       // everyone done with stage kb
        if (kb + 2 < niter) issueKV(kb + 2);
        cp_commit();
    }

    // ---- normalize + write ----
    float i0 = 1.0f / l0, i1 = 1.0f / l1;
    float* o0 = O + (size_t)(qbase + warp * 16 + g) * HIDN + h * HDIM;
    float* o1 = o0 + 8 * HIDN;
    #pragma unroll
    for (int nt = 0; nt < 16; nt++) {
        int col = nt * 8 + 2 * t;
        *(float2*)(o0 + col) = make_float2(oacc[nt][0] * i0, oacc[nt][1] * i0);
        *(float2*)(o1 + col) = make_float2(oacc[nt][2] * i1, oacc[nt][3] * i1);
    }
}

// ============================================================================
// launch
// ============================================================================
extern "C" void kernel_launch(void* const* d_in, const int* in_sizes, int n_in,
                              void* d_out, int out_size)
{
    const float* X   = (const float*)d_in[0];
    const int*   pid = (const int*)  d_in[1];
    const float* Wq  = (const float*)d_in[2];
    const float* Wk  = (const float*)d_in[3];
    const float* Wv  = (const float*)d_in[4];
    const float* Wo  = (const float*)d_in[5];
    float* out = (float*)d_out;

    float *Qb, *Kb, *Vb, *AOb;
    cudaGetSymbolAddress((void**)&Qb,  g_Q);
    cudaGetSymbolAddress((void**)&Kb,  g_K);
    cudaGetSymbolAddress((void**)&Vb,  g_V);
    cudaGetSymbolAddress((void**)&AOb, g_AO);

    cudaFuncSetAttribute(sgemm_tf32,
                         cudaFuncAttributeMaxDynamicSharedMemorySize, GEMM_SMEM);
    cudaFuncSetAttribute(attn_tc,
                         cudaFuncAttributeMaxDynamicSharedMemorySize, ATTN_SMEM);

    dim3 gq(HIDN / 128, SQ / 128);     // 16 x 32
    dim3 gkv(KVW / 128, SQ / 128);     // 4 x 32

    sgemm_tf32<<<gq, 256, GEMM_SMEM>>>(X, Wq, Qb, SQ, HIDN, HIDN);
    sgemm_tf32<<<gkv, 256, GEMM_SMEM>>>(X, Wk, Kb, SQ, KVW, HIDN);
    sgemm_tf32<<<gkv, 256, GEMM_SMEM>>>(X, Wv, Vb, SQ, KVW, HIDN);

    rope_kernel<<<SQ, 256>>>(Qb, Kb, Vb, pid);

    dim3 ga(NHEADS, SQ / 128);         // 16 x 32
    attn_tc<<<ga, 256, ATTN_SMEM>>>(Qb, Kb, Vb, AOb);

    sgemm_tf32<<<gq, 256, GEMM_SMEM>>>(AOb, Wo, out, SQ, HIDN, HIDN);
}

// round 6
// speedup vs baseline: 4.8654x; 1.1775x over previous
#include <cuda_runtime.h>
#include <math.h>

#define SQ    4096
#define HIDN  2048
#define NHEADS 16
#define NKVH   4
#define HDIM   128
#define QKVN  3072            // fused QKV output width
#define QOFF  0
#define KOFF  2048
#define VOFF  2560

// ---------------- scratch (static device globals; no allocation) ----------------
__device__ float g_Xp [SQ * HIDN];        // packed X (A-operand)          32 MB
__device__ float g_Wp [HIDN * QKVN];      // packed Wq|Wk|Wv (B-operand)   24 MB
__device__ float g_Wop[HIDN * HIDN];      // packed Wo (B-operand)         16 MB
__device__ float g_QKV[SQ * QKVN];        // fused QKV output              48 MB
__device__ float g_AO [SQ * HIDN];        // attention output (row-major)  32 MB
__device__ float g_AOp[SQ * HIDN];        // packed AO (A-operand)         32 MB

// ---------------- PTX helpers ----------------
__device__ __forceinline__ unsigned smem_u32(const void* p) {
    return (unsigned)__cvta_generic_to_shared(p);
}
__device__ __forceinline__ void cp_async16(unsigned dst, const void* src) {
    asm volatile("cp.async.cg.shared.global [%0], [%1], 16;\n" :: "r"(dst), "l"(src));
}
__device__ __forceinline__ void cp_commit() {
    asm volatile("cp.async.commit_group;\n");
}
template<int N> __device__ __forceinline__ void cp_wait() {
    asm volatile("cp.async.wait_group %0;\n" :: "n"(N));
}
__device__ __forceinline__ unsigned f2tf(float f) {
    unsigned u;
    asm("cvt.rna.tf32.f32 %0, %1;" : "=r"(u) : "f"(f));
    return u;
}
__device__ __forceinline__ void mma_tf32(float& c0, float& c1, float& c2, float& c3,
                                         unsigned a0, unsigned a1, unsigned a2, unsigned a3,
                                         unsigned b0, unsigned b1) {
    asm volatile("mma.sync.aligned.m16n8k8.row.col.f32.tf32.tf32.f32 "
                 "{%0,%1,%2,%3},{%4,%5,%6,%7},{%8,%9},{%0,%1,%2,%3};"
                 : "+f"(c0), "+f"(c1), "+f"(c2), "+f"(c3)
                 : "r"(a0), "r"(a1), "r"(a2), "r"(a3), "r"(b0), "r"(b1));
}

// ============================================================================
// Operand packing (with tf32 rounding).
// A packed: [mblk][kblk][mt(8)][kt(2)][lane(32)][4]
//   lane(g=l>>2,t=l&3) words: A[r+g][c+t], A[r+8+g][c+t], A[r+g][c+t+4], A[r+8+g][c+t+4]
//   r = mblk*128+mt*16, c = kblk*16+kt*8
// B packed: [nblk][kblk][kt(2)][ng(16)][lane(32)][2]
//   lane words: B[c+t][n+g], B[c+t+4][n+g];  c = kblk*16+kt*8, n = nblk*128+ng*8
// ============================================================================
__global__ __launch_bounds__(256) void pack_A(const float* __restrict__ src,
                                              float* __restrict__ dst, int K)
{
    const int KB = K >> 4;
    long long idx = (long long)blockIdx.x * 256 + threadIdx.x;  // frag index
    int lane = (int)(idx & 31);  long long r0 = idx >> 5;
    int kt = (int)(r0 & 1);      r0 >>= 1;
    int mt = (int)(r0 & 7);      r0 >>= 3;
    int kblk = (int)(r0 % KB);
    int mblk = (int)(r0 / KB);
    int g = lane >> 2, t = lane & 3;
    int r = mblk * 128 + mt * 16 + g;
    int c = kblk * 16 + kt * 8 + t;
    float4 v;
    v.x = __uint_as_float(f2tf(src[(size_t)r * K + c]));
    v.y = __uint_as_float(f2tf(src[(size_t)(r + 8) * K + c]));
    v.z = __uint_as_float(f2tf(src[(size_t)r * K + c + 4]));
    v.w = __uint_as_float(f2tf(src[(size_t)(r + 8) * K + c + 4]));
    ((float4*)dst)[idx] = v;
}

__global__ __launch_bounds__(256) void pack_B(const float* __restrict__ src,
                                              float* __restrict__ dst, int K, int N)
{
    const int KB = K >> 4;
    long long idx = (long long)blockIdx.x * 256 + threadIdx.x;  // frag index
    int lane = (int)(idx & 31);  long long r0 = idx >> 5;
    int ng = (int)(r0 & 15);     r0 >>= 4;
    int kt = (int)(r0 & 1);      r0 >>= 1;
    int kblk = (int)(r0 % KB);
    int nblk = (int)(r0 / KB);
    int g = lane >> 2, t = lane & 3;
    int c = kblk * 16 + kt * 8 + t;
    int n = nblk * 128 + ng * 8 + g;
    float2 v;
    v.x = __uint_as_float(f2tf(src[(size_t)c * N + n]));
    v.y = __uint_as_float(f2tf(src[(size_t)(c + 4) * N + n]));
    ((float2*)dst)[idx] = v;
}

// ============================================================================
// Packed-operand TF32 GEMM: C[M,N] = A @ B (both pre-packed, pre-rounded).
// 128x128 CTA, BK=16, 3-stage cp.async, 8 warps (2m x 4n), warp tile 64x32.
// Inner loop: LDS.128/LDS.64 fragment loads only + HMMA. No cvt.
// ============================================================================
#define GSTG 3
#define GEMM_SMEM (GSTG * 4096 * 4)   // 49152 B

__global__ __launch_bounds__(256, 2) void gemm_packed(
    const float* __restrict__ Ap, const float* __restrict__ Bp,
    float* __restrict__ C, int N, int K)
{
    extern __shared__ float sh[];   // per stage: A 2048 floats | B 2048 floats
    const int KB = K >> 4;
    const int tid  = threadIdx.x;
    const int lane = tid & 31, warp = tid >> 5;
    const int g = lane >> 2, t = lane & 3;
    const int wm = warp >> 2, wn = warp & 3;

    const float* Asrc = Ap + (size_t)blockIdx.y * KB * 2048;
    const float* Bsrc = Bp + (size_t)blockIdx.x * KB * 2048;

    float acc[4][4][4];
    #pragma unroll
    for (int mt = 0; mt < 4; mt++)
        #pragma unroll
        for (int nt = 0; nt < 4; nt++)
            #pragma unroll
            for (int i = 0; i < 4; i++) acc[mt][nt][i] = 0.0f;

    auto issue = [&](int it) {
        float* st = sh + (it % GSTG) * 4096;
        #pragma unroll
        for (int j = 0; j < 4; j++) {
            int ch = tid + 256 * j;                      // 0..1023
            const float* src = (ch < 512) ? (Asrc + (size_t)it * 2048 + ch * 4)
                                          : (Bsrc + (size_t)it * 2048 + (ch - 512) * 4);
            cp_async16(smem_u32(st + ch * 4), src);
        }
    };

    issue(0); cp_commit();
    issue(1); cp_commit();

    for (int it = 0; it < KB; it++) {
        cp_wait<1>();
        __syncthreads();
        if (it + 2 < KB) issue(it + 2);
        cp_commit();

        const float* as = sh + (it % GSTG) * 4096;
        const float* bs = as + 2048;

        #pragma unroll
        for (int kt = 0; kt < 2; kt++) {
            unsigned af[4][4], bf[4][2];
            #pragma unroll
            for (int i = 0; i < 4; i++) {
                int mt = wm * 4 + i;
                uint4 v = *(const uint4*)(as + (mt * 2 + kt) * 128 + lane * 4);
                af[i][0] = v.x; af[i][1] = v.y; af[i][2] = v.z; af[i][3] = v.w;
            }
            #pragma unroll
            for (int nt = 0; nt < 4; nt++) {
                int ng = wn * 4 + nt;
                uint2 v = *(const uint2*)(bs + (kt * 16 + ng) * 64 + lane * 2);
                bf[nt][0] = v.x; bf[nt][1] = v.y;
            }
            #pragma unroll
            for (int mt = 0; mt < 4; mt++)
                #pragma unroll
                for (int nt = 0; nt < 4; nt++)
                    mma_tf32(acc[mt][nt][0], acc[mt][nt][1], acc[mt][nt][2], acc[mt][nt][3],
                             af[mt][0], af[mt][1], af[mt][2], af[mt][3],
                             bf[nt][0], bf[nt][1]);
        }
        __syncthreads();
    }

    const int bm = blockIdx.y * 128, bn = blockIdx.x * 128;
    #pragma unroll
    for (int mt = 0; mt < 4; mt++) {
        int row0 = bm + wm * 64 + mt * 16 + g;
        #pragma unroll
        for (int nt = 0; nt < 4; nt++) {
            int col = bn + wn * 32 + nt * 8 + 2 * t;
            *(float2*)(C + (size_t)row0 * N + col)       = make_float2(acc[mt][nt][0], acc[mt][nt][1]);
            *(float2*)(C + (size_t)(row0 + 8) * N + col) = make_float2(acc[mt][nt][2], acc[mt][nt][3]);
        }
    }
}

// ============================================================================
// RoPE in-place on fused QKV buffer; rounds K and V regions to tf32.
// ============================================================================
__global__ void rope_kernel(float* __restrict__ QKV, const int* __restrict__ pos_ids)
{
    __shared__ float s_inv[64];
    const int s = blockIdx.x;
    if (threadIdx.x < 64) {
        s_inv[threadIdx.x] =
            (float)exp2(-(double)threadIdx.x * (13.287712379549449 / 64.0));
    }
    __syncthreads();

    float* rowp = QKV + (size_t)s * QKVN;
    const float p = (float)pos_ids[s];
    for (int idx = threadIdx.x; idx < (NHEADS + NKVH) * 64; idx += blockDim.x) {
        float* base;
        int d;
        bool isK;
        if (idx < NHEADS * 64) {
            int h = idx >> 6; d = idx & 63;
            base = rowp + QOFF + h * HDIM;
            isK = false;
        } else {
            int tt = idx - NHEADS * 64;
            int h = tt >> 6; d = tt & 63;
            base = rowp + KOFF + h * HDIM;
            isK = true;
        }
        float ang = p * s_inv[d];
        float sn, cs;
        sincosf(ang, &sn, &cs);
        float x1 = base[d], x2 = base[d + 64];
        float r1 = x1 * cs - x2 * sn;
        float r2 = x2 * cs + x1 * sn;
        if (isK) { r1 = __uint_as_float(f2tf(r1)); r2 = __uint_as_float(f2tf(r2)); }
        base[d]      = r1;
        base[d + 64] = r2;
    }
    for (int idx = threadIdx.x; idx < NKVH * HDIM; idx += blockDim.x) {
        float v = rowp[VOFF + idx];
        rowp[VOFF + idx] = __uint_as_float(f2tf(v));
    }
}

// ============================================================================
// Tensor-core flash attention (tf32 mma, fp32 accum, causal, GQA 4:1).
// Reads Q/K/V from fused QKV buffer (row stride 3072).
// ============================================================================
#define KSTR 132
#define VSTR 136
#define PSTR 68
#define ATTN_SMEM ((2*64*KSTR + 2*64*VSTR + 128*PSTR) * 4)   // 172032 B

__global__ __launch_bounds__(256, 1) void attn_tc(
    const float* __restrict__ QKV, float* __restrict__ O)
{
    extern __shared__ float sh[];
    float* Ks = sh;                       // 2 stages [64][132]
    float* Vs = sh + 2 * 64 * KSTR;       // 2 stages [64][136]
    float* Ps = Vs + 2 * 64 * VSTR;       // [128][68]

    const int tid = threadIdx.x, lane = tid & 31, warp = tid >> 5;
    const int g = lane >> 2, t = lane & 3;
    const int h = blockIdx.x;
    const int q = (int)(gridDim.y - 1 - blockIdx.y);   // heavy tiles first
    const int qbase = q * 128;
    const int kvh = h >> 2;
    const int niter = 2 * q + 2;
    const float scale = 0.08838834764831845f;          // 1/sqrt(128)

    // ---- Q fragments into registers (pre-scaled, tf32) ----
    unsigned qa[16][4];
    {
        const float* qp  = QKV + (size_t)(qbase + warp * 16 + g) * QKVN + QOFF + h * HDIM;
        const float* qp8 = qp + 8 * QKVN;
        #pragma unroll
        for (int ks = 0; ks < 16; ks++) {
            qa[ks][0] = f2tf(scale * qp [ks * 8 + t]);
            qa[ks][1] = f2tf(scale * qp8[ks * 8 + t]);
            qa[ks][2] = f2tf(scale * qp [ks * 8 + t + 4]);
            qa[ks][3] = f2tf(scale * qp8[ks * 8 + t + 4]);
        }
    }

    float oacc[16][4];
    #pragma unroll
    for (int nt = 0; nt < 16; nt++)
        #pragma unroll
        for (int i = 0; i < 4; i++) oacc[nt][i] = 0.0f;
    float m0 = -1e30f, m1 = -1e30f, l0 = 0.0f, l1 = 0.0f;

    auto issueKV = [&](int kb) {
        int stage = kb & 1;
        float* kd = Ks + stage * 64 * KSTR;
        float* vd = Vs + stage * 64 * VSTR;
        const float* kg = QKV + (size_t)(kb * 64) * QKVN + KOFF + kvh * HDIM;
        const float* vg = QKV + (size_t)(kb * 64) * QKVN + VOFF + kvh * HDIM;
        #pragma unroll
        for (int j = 0; j < 8; j++) {
            int ch = tid + 256 * j;          // 2048 chunks (64 rows x 32)
            int r = ch >> 5, c = ch & 31;
            cp_async16(smem_u32(kd + r * KSTR + c * 4), kg + (size_t)r * QKVN + c * 4);
        }
        #pragma unroll
        for (int j = 0; j < 8; j++) {
            int ch = tid + 256 * j;
            int r = ch >> 5, c = ch & 31;
            cp_async16(smem_u32(vd + r * VSTR + c * 4), vg + (size_t)r * QKVN + c * 4);
        }
    };
    issueKV(0); cp_commit();
    issueKV(1); cp_commit();                 // niter >= 2 always

    for (int kb = 0; kb < niter; kb++) {
        int stage = kb & 1;
        cp_wait<1>();
        __syncthreads();
        const float* kd = Ks + stage * 64 * KSTR;
        const float* vd = Vs + stage * 64 * VSTR;

        // ---- S = (Q*scale) @ K^T ----
        float sacc[8][4];
        #pragma unroll
        for (int nt = 0; nt < 8; nt++)
            #pragma unroll
            for (int i = 0; i < 4; i++) sacc[nt][i] = 0.0f;

        #pragma unroll
        for (int ks = 0; ks < 16; ks++) {
            #pragma unroll
            for (int nt = 0; nt < 8; nt++) {
                const float* bp = kd + (nt * 8 + g) * KSTR + ks * 8 + t;
                unsigned b0 = __float_as_uint(bp[0]);
                unsigned b1 = __float_as_uint(bp[4]);
                mma_tf32(sacc[nt][0], sacc[nt][1], sacc[nt][2], sacc[nt][3],
                         qa[ks][0], qa[ks][1], qa[ks][2], qa[ks][3], b0, b1);
            }
        }

        // ---- causal mask (only the last two k-tiles intersect the diagonal) ----
        const int row0 = qbase + warp * 16 + g;
        if (kb >= niter - 2) {
            #pragma unroll
            for (int nt = 0; nt < 8; nt++) {
                int c0 = kb * 64 + nt * 8 + 2 * t;
                if (c0     > row0)     sacc[nt][0] = -1e30f;
                if (c0 + 1 > row0)     sacc[nt][1] = -1e30f;
                if (c0     > row0 + 8) sacc[nt][2] = -1e30f;
                if (c0 + 1 > row0 + 8) sacc[nt][3] = -1e30f;
            }
        }

        // ---- online softmax (rows g and g+8; reduce over the 4-lane quad) ----
        float mx0 = -1e30f, mx1 = -1e30f;
        #pragma unroll
        for (int nt = 0; nt < 8; nt++) {
            mx0 = fmaxf(mx0, fmaxf(sacc[nt][0], sacc[nt][1]));
            mx1 = fmaxf(mx1, fmaxf(sacc[nt][2], sacc[nt][3]));
        }
        mx0 = fmaxf(mx0, __shfl_xor_sync(0xffffffffu, mx0, 1));
        mx0 = fmaxf(mx0, __shfl_xor_sync(0xffffffffu, mx0, 2));
        mx1 = fmaxf(mx1, __shfl_xor_sync(0xffffffffu, mx1, 1));
        mx1 = fmaxf(mx1, __shfl_xor_sync(0xffffffffu, mx1, 2));

        float nm0 = fmaxf(m0, mx0), nm1 = fmaxf(m1, mx1);
        float al0 = __expf(m0 - nm0), al1 = __expf(m1 - nm1);
        float s0 = 0.0f, s1 = 0.0f;
        #pragma unroll
        for (int nt = 0; nt < 8; nt++) {
            sacc[nt][0] = __expf(sacc[nt][0] - nm0); s0 += sacc[nt][0];
            sacc[nt][1] = __expf(sacc[nt][1] - nm0); s0 += sacc[nt][1];
            sacc[nt][2] = __expf(sacc[nt][2] - nm1); s1 += sacc[nt][2];
            sacc[nt][3] = __expf(sacc[nt][3] - nm1); s1 += sacc[nt][3];
        }
        s0 += __shfl_xor_sync(0xffffffffu, s0, 1);
        s0 += __shfl_xor_sync(0xffffffffu, s0, 2);
        s1 += __shfl_xor_sync(0xffffffffu, s1, 1);
        s1 += __shfl_xor_sync(0xffffffffu, s1, 2);

        l0 = l0 * al0 + s0;  l1 = l1 * al1 + s1;
        m0 = nm0;            m1 = nm1;
        #pragma unroll
        for (int nt = 0; nt < 16; nt++) {
            oacc[nt][0] *= al0; oacc[nt][1] *= al0;
            oacc[nt][2] *= al1; oacc[nt][3] *= al1;
        }

        // ---- stage P (tf32) to warp-private smem rows ----
        unsigned* pw0 = (unsigned*)(Ps + (warp * 16 + g) * PSTR);
        unsigned* pw1 = pw0 + 8 * PSTR;
        #pragma unroll
        for (int nt = 0; nt < 8; nt++) {
            pw0[nt * 8 + 2 * t]     = f2tf(sacc[nt][0]);
            pw0[nt * 8 + 2 * t + 1] = f2tf(sacc[nt][1]);
            pw1[nt * 8 + 2 * t]     = f2tf(sacc[nt][2]);
            pw1[nt * 8 + 2 * t + 1] = f2tf(sacc[nt][3]);
        }
        __syncwarp();

        // ---- O += P @ V ----
        const unsigned* pr = (const unsigned*)(Ps + (warp * 16 + g) * PSTR);
        #pragma unroll
        for (int ks = 0; ks < 8; ks++) {
            unsigned a0 = pr[ks * 8 + t];
            unsigned a1 = pr[8 * PSTR + ks * 8 + t];
            unsigned a2 = pr[ks * 8 + t + 4];
            unsigned a3 = pr[8 * PSTR + ks * 8 + t + 4];
            #pragma unroll
            for (int nt = 0; nt < 16; nt++) {
                const float* vp = vd + (ks * 8 + t) * VSTR + nt * 8 + g;
                unsigned b0 = __float_as_uint(vp[0]);
                unsigned b1 = __float_as_uint(vp[4 * VSTR]);
                mma_tf32(oacc[nt][0], oacc[nt][1], oacc[nt][2], oacc[nt][3],
                         a0, a1, a2, a3, b0, b1);
            }
        }

        __syncthreads();                       // everyone done with stage kb
        if (kb + 2 < niter) issueKV(kb + 2);
        cp_commit();
    }

    // ---- normalize + write (row-major AO) ----
    float i0 = 1.0f / l0, i1 = 1.0f / l1;
    float* o0 = O + (size_t)(qbase + warp * 16 + g) * HIDN + h * HDIM;
    float* o1 = o0 + 8 * HIDN;
    #pragma unroll
    for (int nt = 0; nt < 16; nt++) {
        int col = nt * 8 + 2 * t;
        *(float2*)(o0 + col) = make_float2(oacc[nt][0] * i0, oacc[nt][1] * i0);
        *(float2*)(o1 + col) = make_float2(oacc[nt][2] * i1, oacc[nt][3] * i1);
    }
}

// ============================================================================
// launch
// ============================================================================
extern "C" void kernel_launch(void* const* d_in, const int* in_sizes, int n_in,
                              void* d_out, int out_size)
{
    const float* X   = (const float*)d_in[0];
    const int*   pid = (const int*)  d_in[1];
    const float* Wq  = (const float*)d_in[2];
    const float* Wk  = (const float*)d_in[3];
    const float* Wv  = (const float*)d_in[4];
    const float* Wo  = (const float*)d_in[5];
    float* out = (float*)d_out;

    float *Xp, *Wp, *Wop, *QKV, *AO, *AOp;
    cudaGetSymbolAddress((void**)&Xp,  g_Xp);
    cudaGetSymbolAddress((void**)&Wp,  g_Wp);
    cudaGetSymbolAddress((void**)&Wop, g_Wop);
    cudaGetSymbolAddress((void**)&QKV, g_QKV);
    cudaGetSymbolAddress((void**)&AO,  g_AO);
    cudaGetSymbolAddress((void**)&AOp, g_AOp);

    cudaFuncSetAttribute(gemm_packed,
                         cudaFuncAttributeMaxDynamicSharedMemorySize, GEMM_SMEM);
    cudaFuncSetAttribute(attn_tc,
                         cudaFuncAttributeMaxDynamicSharedMemorySize, ATTN_SMEM);

    const int KB = HIDN / 16;   // 128

    // ---- pack operands (tf32 rounding applied here, once) ----
    pack_A<<<(SQ * HIDN / 4) / 256, 256>>>(X, Xp, HIDN);                      // X
    pack_B<<<(HIDN * HIDN / 2) / 256, 256>>>(Wq, Wp, HIDN, HIDN);             // nblk 0..15
    pack_B<<<(HIDN * 512  / 2) / 256, 256>>>(Wk, Wp + (size_t)16 * KB * 2048, HIDN, 512);
    pack_B<<<(HIDN * 512  / 2) / 256, 256>>>(Wv, Wp + (size_t)20 * KB * 2048, HIDN, 512);
    pack_B<<<(HIDN * HIDN / 2) / 256, 256>>>(Wo, Wop, HIDN, HIDN);

    // ---- fused QKV projection ----
    dim3 gqkv(QKVN / 128, SQ / 128);   // 24 x 32
    gemm_packed<<<gqkv, 256, GEMM_SMEM>>>(Xp, Wp, QKV, QKVN, HIDN);

    rope_kernel<<<SQ, 256>>>(QKV, pid);

    dim3 ga(NHEADS, SQ / 128);         // 16 x 32
    attn_tc<<<ga, 256, ATTN_SMEM>>>(QKV, AO);

    // ---- output projection ----
    pack_A<<<(SQ * HIDN / 4) / 256, 256>>>(AO, AOp, HIDN);
    dim3 go(HIDN / 128, SQ / 128);     // 16 x 32
    gemm_packed<<<go, 256, GEMM_SMEM>>>(AOp, Wop, out, HIDN, HIDN);
}

// round 9
// speedup vs baseline: 9.3871x; 1.9294x over previous
#include <cuda_runtime.h>
#include <cuda_fp16.h>
#include <math.h>
#include <stdint.h>

#define SQ    4096
#define HIDN  2048
#define NHEADS 16
#define NKVH   4
#define HDIM   128
#define QKVN  3072            // fused QKV output width
#define QOFF  0
#define KOFF  2048
#define VOFF  2560
#define KBLKS 64              // HIDN/32 k-tiles for GEMMs

// ---------------- scratch (static device globals; no allocation) ----------------
__device__ __half g_Xp [SQ * HIDN];        // X as fp16 A-fragments      16 MB
__device__ __half g_Wp [HIDN * QKVN];      // Wq|Wk|Wv fp16 B-fragments  12 MB
__device__ __half g_Wop[HIDN * HIDN];      // Wo fp16 B-fragments         8 MB
__device__ float  g_QKV[SQ * QKVN];        // fused QKV output (f32)     48 MB
__device__ __half g_Kh [NKVH * SQ * HDIM]; // rope'd K, fragment-packed   4 MB
__device__ __half g_Vh [NKVH * SQ * HDIM]; // V, fragment-packed          4 MB
__device__ float  g_AO [SQ * HIDN];        // attention output (f32)     32 MB
__device__ __half g_AOp[SQ * HIDN];        // AO as fp16 A-fragments     16 MB

// ---------------- PTX helpers ----------------
__device__ __forceinline__ unsigned smem_u32(const void* p) {
    return (unsigned)__cvta_generic_to_shared(p);
}
__device__ __forceinline__ void cp_async16(unsigned dst, const void* src) {
    asm volatile("cp.async.cg.shared.global [%0], [%1], 16;\n" :: "r"(dst), "l"(src));
}
__device__ __forceinline__ void cp_commit() {
    asm volatile("cp.async.commit_group;\n");
}
template<int N> __device__ __forceinline__ void cp_wait() {
    asm volatile("cp.async.wait_group %0;\n" :: "n"(N));
}
__device__ __forceinline__ unsigned h2u(float lo, float hi) {
    __half2 h = __floats2half2_rn(lo, hi);
    return *(unsigned*)&h;
}
__device__ __forceinline__ void mma_f16(float& c0, float& c1, float& c2, float& c3,
                                        unsigned a0, unsigned a1, unsigned a2, unsigned a3,
                                        unsigned b0, unsigned b1) {
    asm volatile("mma.sync.aligned.m16n8k16.row.col.f32.f16.f16.f32 "
                 "{%0,%1,%2,%3},{%4,%5,%6,%7},{%8,%9},{%0,%1,%2,%3};"
                 : "+f"(c0), "+f"(c1), "+f"(c2), "+f"(c3)
                 : "r"(a0), "r"(a1), "r"(a2), "r"(a3), "r"(b0), "r"(b1));
}

// ============================================================================
// Pack kernels: emit fp16 mma fragments.
// A frag (m16n8k16): per [mblk][kblk][mt(8)][kt(2)][lane] 4 u32 (8 halves):
//   a0={A[r+g][c+2t],+1} a1={A[r+8+g][..]} a2={A[r+g][c+8+2t],+1} a3={r+8+g,c+8..}
//   r=mblk*128+mt*16, c=kblk*32+kt*16
// B frag: per [nblk][kblk][kt(2)][ng(16)][lane] 2 u32 (4 halves):
//   b0={B[c+2t][n],B[c+2t+1][n]}  b1={B[c+8+2t][n],B[c+9+2t][n]}   n=nblk*128+ng*8+g
// ============================================================================
__global__ __launch_bounds__(256) void pack_A_h(const float* __restrict__ src,
                                                __half* __restrict__ dst, int K)
{
    const int KB = K >> 5;
    long long idx = (long long)blockIdx.x * 256 + threadIdx.x;
    int lane = (int)(idx & 31); long long f = idx >> 5;
    int kt = (int)(f & 1);  f >>= 1;
    int mt = (int)(f & 7);  f >>= 3;
    int kblk = (int)(f % KB);
    int mblk = (int)(f / KB);
    int g = lane >> 2, t = lane & 3;
    int r = mblk * 128 + mt * 16 + g;
    int c = kblk * 32 + kt * 16 + 2 * t;
    const float* p0 = src + (size_t)r * K + c;
    const float* p1 = src + (size_t)(r + 8) * K + c;
    uint4 v;
    v.x = h2u(p0[0], p0[1]);
    v.y = h2u(p1[0], p1[1]);
    v.z = h2u(p0[8], p0[9]);
    v.w = h2u(p1[8], p1[9]);
    ((uint4*)dst)[idx] = v;
}

__global__ __launch_bounds__(256) void pack_B_h(const float* __restrict__ src,
                                                __half* __restrict__ dst, int K, int N)
{
    const int KB = K >> 5;
    long long idx = (long long)blockIdx.x * 256 + threadIdx.x;
    int lane = (int)(idx & 31); long long f = idx >> 5;
    int ng = (int)(f & 15); f >>= 4;
    int kt = (int)(f & 1);  f >>= 1;
    int kblk = (int)(f % KB);
    int nblk = (int)(f / KB);
    int g = lane >> 2, t = lane & 3;
    int n = nblk * 128 + ng * 8 + g;
    int c = kblk * 32 + kt * 16 + 2 * t;
    uint2 v;
    v.x = h2u(src[(size_t)c * N + n],       src[(size_t)(c + 1) * N + n]);
    v.y = h2u(src[(size_t)(c + 8) * N + n], src[(size_t)(c + 9) * N + n]);
    ((uint2*)dst)[idx] = v;
}

// ============================================================================
// FP16 tensor-core GEMM: C[M,N] = A @ B, pre-packed fragments.
// 128x128 CTA, BK=32, 3-stage cp.async, 8 warps (2m x 4n), m16n8k16 mma.
// ============================================================================
#define GSTG 3
#define STAGE_H 8192                    // A 4096 + B 4096 halfs = 16KB
#define GEMM_SMEM (GSTG * STAGE_H * 2)  // 49152 B

__global__ __launch_bounds__(256, 2) void gemm_h(
    const __half* __restrict__ Ap, const __half* __restrict__ Bp,
    float* __restrict__ C, int N, int KB)
{
    extern __shared__ __align__(16) __half shh[];
    const int tid  = threadIdx.x;
    const int lane = tid & 31, warp = tid >> 5;
    const int g = lane >> 2, t = lane & 3;
    const int wm = warp >> 2, wn = warp & 3;

    const __half* Abase = Ap + (size_t)blockIdx.y * KB * 4096;
    const __half* Bbase = Bp + (size_t)blockIdx.x * KB * 4096;

    float acc[4][4][4];
    #pragma unroll
    for (int mt = 0; mt < 4; mt++)
        #pragma unroll
        for (int nt = 0; nt < 4; nt++)
            #pragma unroll
            for (int i = 0; i < 4; i++) acc[mt][nt][i] = 0.0f;

    auto issue = [&](int it) {
        __half* st = shh + (it % GSTG) * STAGE_H;
        const __half* at = Abase + (size_t)it * 4096;
        const __half* bt = Bbase + (size_t)it * 4096;
        #pragma unroll
        for (int j = 0; j < 4; j++) {
            int ch = tid + 256 * j;                       // 1024 x 16B
            const __half* src = (ch < 512) ? (at + ch * 8) : (bt + (ch - 512) * 8);
            cp_async16(smem_u32(st + ch * 8), src);
        }
    };

    issue(0); cp_commit();
    issue(1); cp_commit();

    for (int it = 0; it < KB; it++) {
        cp_wait<1>();
        __syncthreads();
        if (it + 2 < KB) issue(it + 2);
        cp_commit();

        const __half* st = shh + (it % GSTG) * STAGE_H;
        const uint4* af4 = (const uint4*)st;
        const uint2* bf2 = (const uint2*)(st + 4096);

        #pragma unroll
        for (int kt = 0; kt < 2; kt++) {
            unsigned af[4][4], bf[4][2];
            #pragma unroll
            for (int i = 0; i < 4; i++) {
                int mt = wm * 4 + i;
                uint4 v = af4[(mt * 2 + kt) * 32 + lane];
                af[i][0] = v.x; af[i][1] = v.y; af[i][2] = v.z; af[i][3] = v.w;
            }
            #pragma unroll
            for (int nt = 0; nt < 4; nt++) {
                int ng = wn * 4 + nt;
                uint2 v = bf2[(kt * 16 + ng) * 32 + lane];
                bf[nt][0] = v.x; bf[nt][1] = v.y;
            }
            #pragma unroll
            for (int mt = 0; mt < 4; mt++)
                #pragma unroll
                for (int nt = 0; nt < 4; nt++)
                    mma_f16(acc[mt][nt][0], acc[mt][nt][1], acc[mt][nt][2], acc[mt][nt][3],
                            af[mt][0], af[mt][1], af[mt][2], af[mt][3],
                            bf[nt][0], bf[nt][1]);
        }
        __syncthreads();
    }

    const int bm = blockIdx.y * 128, bn = blockIdx.x * 128;
    #pragma unroll
    for (int mt = 0; mt < 4; mt++) {
        int row0 = bm + wm * 64 + mt * 16 + g;
        #pragma unroll
        for (int nt = 0; nt < 4; nt++) {
            int col = bn + wn * 32 + nt * 8 + 2 * t;
            *(float2*)(C + (size_t)row0 * N + col)       = make_float2(acc[mt][nt][0], acc[mt][nt][1]);
            *(float2*)(C + (size_t)(row0 + 8) * N + col) = make_float2(acc[mt][nt][2], acc[mt][nt][3]);
        }
    }
}

// ============================================================================
// RoPE: Q in-place (f32) in QKV; K (rope'd) and V written as fragment-packed
// fp16 tiles for the attention kernel.
// ============================================================================
__device__ __forceinline__ void storeKfrag(__half* tile, int n, int dd, float v) {
    int ks = dd >> 4, r = dd & 15;
    int reg = r >> 3, t = (r & 7) >> 1, lo = r & 1;
    int lane = (n & 7) * 4 + t, nt = n >> 3;
    tile[(((ks * 8 + nt) * 32 + lane) << 2) + reg * 2 + lo] = __float2half_rn(v);
}
__device__ __forceinline__ void storeVfrag(__half* tile, int kk, int dd, float v) {
    int ks = kk >> 4, r = kk & 15;
    int reg = r >> 3, t = (r & 7) >> 1, lo = r & 1;
    int lane = (dd & 7) * 4 + t, nt = dd >> 3;
    tile[(((ks * 16 + nt) * 32 + lane) << 2) + reg * 2 + lo] = __float2half_rn(v);
}

__global__ void rope_kernel(float* __restrict__ QKV, __half* __restrict__ Kh,
                            __half* __restrict__ Vh, const int* __restrict__ pos_ids)
{
    __shared__ float s_inv[64];
    const int s = blockIdx.x;
    if (threadIdx.x < 64) {
        s_inv[threadIdx.x] =
            (float)exp2(-(double)threadIdx.x * (13.287712379549449 / 64.0));
    }
    __syncthreads();

    float* rowp = QKV + (size_t)s * QKVN;
    const float p = (float)pos_ids[s];
    const int kb = s >> 6, n = s & 63;

    for (int idx = threadIdx.x; idx < (NHEADS + NKVH) * 64; idx += blockDim.x) {
        if (idx < NHEADS * 64) {
            int h = idx >> 6, d = idx & 63;
            float* base = rowp + QOFF + h * HDIM;
            float ang = p * s_inv[d];
            float sn, cs;
            sincosf(ang, &sn, &cs);
            float x1 = base[d], x2 = base[d + 64];
            base[d]      = x1 * cs - x2 * sn;
            base[d + 64] = x2 * cs + x1 * sn;
        } else {
            int tt = idx - NHEADS * 64;
            int h = tt >> 6, d = tt & 63;
            const float* base = rowp + KOFF + h * HDIM;
            float ang = p * s_inv[d];
            float sn, cs;
            sincosf(ang, &sn, &cs);
            float x1 = base[d], x2 = base[d + 64];
            __half* tile = Kh + (size_t)(h * 64 + kb) * 8192;
            storeKfrag(tile, n, d,      x1 * cs - x2 * sn);
            storeKfrag(tile, n, d + 64, x2 * cs + x1 * sn);
        }
    }
    for (int idx = threadIdx.x; idx < NKVH * HDIM; idx += blockDim.x) {
        int h = idx >> 7, dd = idx & 127;
        __half* tile = Vh + (size_t)(h * 64 + kb) * 8192;
        storeVfrag(tile, n, dd, rowp[VOFF + idx]);
    }
}

// ============================================================================
// FP16 tensor-core flash attention (f32 softmax/accum, causal, GQA 4:1).
// BQ=128 (8 warps x m16), BK=64. Q regs; K/V fragment-packed, double-buffered.
// P stays in registers (C-layout of S == A-layout of P for fp16 k16).
// ============================================================================
#define ATTN_SMEM (4 * 8192 * 2)   // 2 K stages + 2 V stages, 16KB each = 64KB

__global__ __launch_bounds__(256, 1) void attn_h(
    const float* __restrict__ QKV, const __half* __restrict__ Kh,
    const __half* __restrict__ Vh, float* __restrict__ O)
{
    extern __shared__ __align__(16) __half shh[];
    const int tid = threadIdx.x, lane = tid & 31, warp = tid >> 5;
    const int g = lane >> 2, t = lane & 3;
    const int h = blockIdx.x;
    const int q = (int)(gridDim.y - 1 - blockIdx.y);   // heavy tiles first
    const int qbase = q * 128;
    const int kvh = h >> 2;
    const int niter = 2 * q + 2;
    const float scale = 0.08838834764831845f;          // 1/sqrt(128)

    unsigned qa[8][4];
    {
        const float* qp  = QKV + (size_t)(qbase + warp * 16 + g) * QKVN + QOFF + h * HDIM;
        const float* qp8 = qp + 8 * QKVN;
        #pragma unroll
        for (int ks = 0; ks < 8; ks++) {
            int c = ks * 16 + 2 * t;
            qa[ks][0] = h2u(scale * qp [c],     scale * qp [c + 1]);
            qa[ks][1] = h2u(scale * qp8[c],     scale * qp8[c + 1]);
            qa[ks][2] = h2u(scale * qp [c + 8], scale * qp [c + 9]);
            qa[ks][3] = h2u(scale * qp8[c + 8], scale * qp8[c + 9]);
        }
    }

    float oacc[16][4];
    #pragma unroll
    for (int nt = 0; nt < 16; nt++)
        #pragma unroll
        for (int i = 0; i < 4; i++) oacc[nt][i] = 0.0f;
    float m0 = -1e30f, m1 = -1e30f, l0 = 0.0f, l1 = 0.0f;

    auto issueKV = [&](int kb) {
        int stage = kb & 1;
        __half* kd = shh + stage * 8192;
        __half* vd = shh + 16384 + stage * 8192;
        const __half* kg = Kh + (size_t)(kvh * 64 + kb) * 8192;
        const __half* vg = Vh + (size_t)(kvh * 64 + kb) * 8192;
        #pragma unroll
        for (int j = 0; j < 4; j++) {
            int ch = tid + 256 * j;                 // 1024 x 16B
            cp_async16(smem_u32(kd + ch * 8), kg + ch * 8);
        }
        #pragma unroll
        for (int j = 0; j < 4; j++) {
            int ch = tid + 256 * j;
            cp_async16(smem_u32(vd + ch * 8), vg + ch * 8);
        }
    };
    issueKV(0); cp_commit();
    issueKV(1); cp_commit();

    for (int kb = 0; kb < niter; kb++) {
        int stage = kb & 1;
        cp_wait<1>();
        __syncthreads();
        const uint2* kf = (const uint2*)(shh + stage * 8192);
        const uint2* vf = (const uint2*)(shh + 16384 + stage * 8192);

        float sacc[8][4];
        #pragma unroll
        for (int nt = 0; nt < 8; nt++)
            #pragma unroll
            for (int i = 0; i < 4; i++) sacc[nt][i] = 0.0f;

        #pragma unroll
        for (int ks = 0; ks < 8; ks++) {
            #pragma unroll
            for (int nt = 0; nt < 8; nt++) {
                uint2 b = kf[(ks * 8 + nt) * 32 + lane];
                mma_f16(sacc[nt][0], sacc[nt][1], sacc[nt][2], sacc[nt][3],
                        qa[ks][0], qa[ks][1], qa[ks][2], qa[ks][3], b.x, b.y);
            }
        }

        const int row0 = qbase + warp * 16 + g;
        if (kb >= niter - 2) {
            #pragma unroll
            for (int nt = 0; nt < 8; nt++) {
                int c0 = kb * 64 + nt * 8 + 2 * t;
                if (c0     > row0)     sacc[nt][0] = -1e30f;
                if (c0 + 1 > row0)     sacc[nt][1] = -1e30f;
                if (c0     > row0 + 8) sacc[nt][2] = -1e30f;
                if (c0 + 1 > row0 + 8) sacc[nt][3] = -1e30f;
            }
        }

        float mx0 = -1e30f, mx1 = -1e30f;
        #pragma unroll
        for (int nt = 0; nt < 8; nt++) {
            mx0 = fmaxf(mx0, fmaxf(sacc[nt][0], sacc[nt][1]));
            mx1 = fmaxf(mx1, fmaxf(sacc[nt][2], sacc[nt][3]));
        }
        mx0 = fmaxf(mx0, __shfl_xor_sync(0xffffffffu, mx0, 1));
        mx0 = fmaxf(mx0, __shfl_xor_sync(0xffffffffu, mx0, 2));
        mx1 = fmaxf(mx1, __shfl_xor_sync(0xffffffffu, mx1, 1));
        mx1 = fmaxf(mx1, __shfl_xor_sync(0xffffffffu, mx1, 2));

        float nm0 = fmaxf(m0, mx0), nm1 = fmaxf(m1, mx1);
        float al0 = __expf(m0 - nm0), al1 = __expf(m1 - nm1);
        float s0 = 0.0f, s1 = 0.0f;
        #pragma unroll
        for (int nt = 0; nt < 8; nt++) {
            sacc[nt][0] = __expf(sacc[nt][0] - nm0); s0 += sacc[nt][0];
            sacc[nt][1] = __expf(sacc[nt][1] - nm0); s0 += sacc[nt][1];
            sacc[nt][2] = __expf(sacc[nt][2] - nm1); s1 += sacc[nt][2];
            sacc[nt][3] = __expf(sacc[nt][3] - nm1); s1 += sacc[nt][3];
        }
        s0 += __shfl_xor_sync(0xffffffffu, s0, 1);
        s0 += __shfl_xor_sync(0xffffffffu, s0, 2);
        s1 += __shfl_xor_sync(0xffffffffu, s1, 1);
        s1 += __shfl_xor_sync(0xffffffffu, s1, 2);

        l0 = l0 * al0 + s0;  l1 = l1 * al1 + s1;
        m0 = nm0;            m1 = nm1;
        #pragma unroll
        for (int nt = 0; nt < 16; nt++) {
            oacc[nt][0] *= al0; oacc[nt][1] *= al0;
            oacc[nt][2] *= al1; oacc[nt][3] *= al1;
        }

        // ---- P fragments directly from S registers (no smem round-trip) ----
        unsigned pa[4][4];
        #pragma unroll
        for (int ksp = 0; ksp < 4; ksp++) {
            pa[ksp][0] = h2u(sacc[2 * ksp][0],     sacc[2 * ksp][1]);
            pa[ksp][1] = h2u(sacc[2 * ksp][2],     sacc[2 * ksp][3]);
            pa[ksp][2] = h2u(sacc[2 * ksp + 1][0], sacc[2 * ksp + 1][1]);
            pa[ksp][3] = h2u(sacc[2 * ksp + 1][2], sacc[2 * ksp + 1][3]);
        }

        // ---- O += P @ V ----
        #pragma unroll
        for (int ksp = 0; ksp < 4; ksp++) {
            #pragma unroll
            for (int nt = 0; nt < 16; nt++) {
                uint2 b = vf[(ksp * 16 + nt) * 32 + lane];
                mma_f16(oacc[nt][0], oacc[nt][1], oacc[nt][2], oacc[nt][3],
                        pa[ksp][0], pa[ksp][1], pa[ksp][2], pa[ksp][3], b.x, b.y);
            }
        }

        __syncthreads();
        if (kb + 2 < niter) issueKV(kb + 2);
        cp_commit();
    }

    float i0 = 1.0f / l0, i1 = 1.0f / l1;
    float* o0 = O + (size_t)(qbase + warp * 16 + g) * HIDN + h * HDIM;
    float* o1 = o0 + 8 * HIDN;
    #pragma unroll
    for (int nt = 0; nt < 16; nt++) {
        int col = nt * 8 + 2 * t;
        *(float2*)(o0 + col) = make_float2(oacc[nt][0] * i0, oacc[nt][1] * i0);
        *(float2*)(o1 + col) = make_float2(oacc[nt][2] * i1, oacc[nt][3] * i1);
    }
}

// ============================================================================
// launch
// ============================================================================
extern "C" void kernel_launch(void* const* d_in, const int* in_sizes, int n_in,
                              void* d_out, int out_size)
{
    const float* X   = (const float*)d_in[0];
    const int*   pid = (const int*)  d_in[1];
    const float* Wq  = (const float*)d_in[2];
    const float* Wk  = (const float*)d_in[3];
    const float* Wv  = (const float*)d_in[4];
    const float* Wo  = (const float*)d_in[5];
    float* out = (float*)d_out;

    __half *Xp, *Wp, *Wop, *Kh, *Vh, *AOp;
    float *QKV, *AO;
    cudaGetSymbolAddress((void**)&Xp,  g_Xp);
    cudaGetSymbolAddress((void**)&Wp,  g_Wp);
    cudaGetSymbolAddress((void**)&Wop, g_Wop);
    cudaGetSymbolAddress((void**)&QKV, g_QKV);
    cudaGetSymbolAddress((void**)&Kh,  g_Kh);
    cudaGetSymbolAddress((void**)&Vh,  g_Vh);
    cudaGetSymbolAddress((void**)&AO,  g_AO);
    cudaGetSymbolAddress((void**)&AOp, g_AOp);

    cudaFuncSetAttribute(gemm_h,
                         cudaFuncAttributeMaxDynamicSharedMemorySize, GEMM_SMEM);
    cudaFuncSetAttribute(attn_h,
                         cudaFuncAttributeMaxDynamicSharedMemorySize, ATTN_SMEM);

    // ---- pack operands to fp16 fragments ----
    // pack_A_h: 8 halves/thread -> total/8.  pack_B_h: 4 halves/thread -> total/4.
    pack_A_h<<<(SQ * HIDN / 8) / 256, 256>>>(X, Xp, HIDN);
    pack_B_h<<<(HIDN * HIDN / 4) / 256, 256>>>(Wq, Wp, HIDN, HIDN);                       // nblk 0-15
    pack_B_h<<<(HIDN * 512  / 4) / 256, 256>>>(Wk, Wp + (size_t)16 * KBLKS * 4096, HIDN, 512);
    pack_B_h<<<(HIDN * 512  / 4) / 256, 256>>>(Wv, Wp + (size_t)20 * KBLKS * 4096, HIDN, 512);
    pack_B_h<<<(HIDN * HIDN / 4) / 256, 256>>>(Wo, Wop, HIDN, HIDN);

    // ---- fused QKV projection ----
    gemm_h<<<dim3(QKVN / 128, SQ / 128), 256, GEMM_SMEM>>>(Xp, Wp, QKV, QKVN, KBLKS);

    // ---- RoPE + K/V fragment packing ----
    rope_kernel<<<SQ, 256>>>(QKV, Kh, Vh, pid);

    // ---- attention ----
    dim3 ga(NHEADS, SQ / 128);
    attn_h<<<ga, 256, ATTN_SMEM>>>(QKV, Kh, Vh, AO);

    // ---- output projection ----
    pack_A_h<<<(SQ * HIDN / 8) / 256, 256>>>(AO, AOp, HIDN);
    gemm_h<<<dim3(HIDN / 128, SQ / 128), 256, GEMM_SMEM>>>(AOp, Wop, out, HIDN, KBLKS);
}